// round 15
// baseline (speedup 1.0000x reference)
#include <cuda_runtime.h>
#include <cuda_bf16.h>
#include <cstdint>

#define BATCH 512
#define TLEN  512
#define IDIM  128
#define HDIM  512
#define NGRP  32                          // CTAs per batch-group barrier

#define OFF_BSUM  0
#define OFF_XCH   1024                    // 4 pairs * 2 halves * 4608B
#define OFF_WH    38912
#define OFF_WL    (OFF_WH + 81920)
#define SMEM_BYTES (OFF_WL + 81920)       // 202752

__device__ float    g_h[2][BATCH * HDIM];
__device__ unsigned g_count4[4], g_gen4[4];

__device__ __forceinline__ uint32_t smem_u32(const void* p) {
    uint32_t a;
    asm("{ .reg .u64 t; cvta.to.shared.u64 t, %1; cvt.u32.u64 %0, t; }" : "=r"(a) : "l"(p));
    return a;
}
#define SWZ(o) ((o) ^ (((o) >> 3) & 0x70))

__device__ __forceinline__ void ldm4(uint32_t* r, uint32_t addr) {
    asm volatile("ldmatrix.sync.aligned.m8n8.x4.shared.b16 {%0,%1,%2,%3}, [%4];"
        : "=r"(r[0]), "=r"(r[1]), "=r"(r[2]), "=r"(r[3]) : "r"(addr));
}
__device__ __forceinline__ void mma16816(float* d, const uint32_t* a, const uint32_t* b) {
    asm volatile("mma.sync.aligned.m16n8k16.row.col.f32.bf16.bf16.f32 "
        "{%0,%1,%2,%3},{%4,%5,%6,%7},{%8,%9},{%0,%1,%2,%3};"
        : "+f"(d[0]), "+f"(d[1]), "+f"(d[2]), "+f"(d[3])
        : "r"(a[0]), "r"(a[1]), "r"(a[2]), "r"(a[3]), "r"(b[0]), "r"(b[1]));
}

// ---- per-batch-group barrier: acq_rel arrival + release/acquire gen ----
__device__ __forceinline__ void gb_arrive(int tid, int grp, unsigned target) {
    if (tid == 0) {
        unsigned old;
        asm volatile("atom.acq_rel.gpu.global.add.u32 %0, [%1], 1;"
                     : "=r"(old) : "l"(&g_count4[grp]) : "memory");
        if (old == NGRP - 1) {
            asm volatile("st.relaxed.gpu.global.u32 [%0], %1;"
                         :: "l"(&g_count4[grp]), "r"(0u) : "memory");
            asm volatile("st.release.gpu.global.u32 [%0], %1;"
                         :: "l"(&g_gen4[grp]), "r"(target) : "memory");
        }
    }
}
__device__ __forceinline__ void gb_wait(int tid, int grp, unsigned target) {
    if (tid == 0) {
        unsigned g;
        do {
            asm volatile("ld.acquire.gpu.global.u32 %0, [%1];"
                         : "=r"(g) : "l"(&g_gen4[grp]) : "memory");
        } while ((int)(g - target) < 0);
    }
    __syncthreads();
}

// hi/lo bf16 split of a float4, stored as two 8-byte shared words (weights).
__device__ __forceinline__ void cvt_sts(float4 v, uint32_t ah, uint32_t al) {
    __nv_bfloat162 h0 = __floats2bfloat162_rn(v.x, v.y);
    __nv_bfloat162 h1 = __floats2bfloat162_rn(v.z, v.w);
    float lx = v.x - __bfloat162float(h0.x), ly = v.y - __bfloat162float(h0.y);
    float lz = v.z - __bfloat162float(h1.x), lw = v.w - __bfloat162float(h1.y);
    __nv_bfloat162 l0 = __floats2bfloat162_rn(lx, ly);
    __nv_bfloat162 l1 = __floats2bfloat162_rn(lz, lw);
    uint64_t hv = ((uint64_t)*(uint32_t*)&h1 << 32) | *(uint32_t*)&h0;
    uint64_t lv = ((uint64_t)*(uint32_t*)&l1 << 32) | *(uint32_t*)&l0;
    asm volatile("st.shared.b64 [%0], %1;" :: "r"(ah), "l"(hv) : "memory");
    asm volatile("st.shared.b64 [%0], %1;" :: "r"(al), "l"(lv) : "memory");
}

__device__ __forceinline__ float sig_(float x) { return 1.0f / (1.0f + __expf(-x)); }
__device__ __forceinline__ float tnh_(float x) { return 2.0f / (1.0f + __expf(-2.0f * x)) - 1.0f; }

__global__ void __launch_bounds__(256, 1) lstm_mma10(
    const float* __restrict__ x,
    const float* __restrict__ eWih, const float* __restrict__ eWhh,
    const float* __restrict__ ebih, const float* __restrict__ ebhh,
    const float* __restrict__ dWih, const float* __restrict__ dWhh,
    const float* __restrict__ dbih, const float* __restrict__ dbhh,
    const float* __restrict__ fcW,  const float* __restrict__ fcb,
    float* __restrict__ out)
{
    extern __shared__ __align__(1024) char smem[];
    const uint32_t sb = smem_u32(smem);
    const int tid = threadIdx.x, wid = tid >> 5, lane = tid & 31;
    const int p  = wid >> 1;            // pair/tile 0..3 -> rows 32p..32p+31
    const int kp = wid & 1;             // k-parity within pair
    const int by = blockIdx.y;          // batch group (barrier group)
    const int jb = blockIdx.x * 16;     // h-col base
    const int b0 = by * 128;            // batch base
    const int lq = lane >> 2;           // 0..7
    const int lr = (lane & 3) << 1;     // 0,2,4,6

    float* bsum = (float*)(smem + OFF_BSUM);

    unsigned gbase = 0;
    if (tid == 0) gbase = *(volatile unsigned*)&g_gen4[by];

    // zero this CTA's slice of h0
    for (int i = tid; i < 2048; i += 256) {
        int r = i >> 5, c = i & 31;
        g_h[0][(size_t)(b0 + r) * HDIM + jb + c] = 0.0f;
    }
    float cst[8];
    #pragma unroll
    for (int j = 0; j < 8; ++j) cst[j] = 0.0f;

    gb_arrive(tid, by, gbase + 1);
    gb_wait(tid, by, gbase + 1);

    float2 bufA[16], bufB[16];

    #pragma unroll 1
    for (int s = 0; s < 2 * TLEN; ++s) {
        const int dec = (s >= TLEN) ? 1 : 0;
        const int t = dec ? s - TLEN : s;
        const float* hin  = g_h[s & 1];
        float*       hout = g_h[(s + 1) & 1];

        // ---- per-phase weight + bias preload (hi/lo bf16 in SMEM) ----
        if (s == 0 || s == TLEN) {
            const float* Wih = dec ? dWih : eWih;
            const float* Whh = dec ? dWhh : eWhh;
            const float* bi  = dec ? dbih : ebih;
            const float* bh  = dec ? dbhh : ebhh;
            __syncthreads();
            #pragma unroll 1
            for (int i = tid; i < 10240; i += 256) {   // 64 rows x 160 float4
                int rl = i / 160, k4 = i % 160;
                int c = k4 >> 4, kin = k4 & 15;
                int grow = (rl >> 4) * HDIM + jb + (rl & 15);
                const float* sp = (c < 2) ? (Wih + (size_t)grow * IDIM + c * 64 + kin * 4)
                                          : (Whh + (size_t)grow * HDIM + (c - 2) * 64 + kin * 4);
                float4 v = *(const float4*)sp;
                uint32_t off = (uint32_t)c * 8192u + SWZ((uint32_t)rl * 128u + (uint32_t)kin * 8u);
                cvt_sts(v, sb + OFF_WH + off, sb + OFF_WL + off);
            }
            if (tid < 64) {
                int g = tid >> 4, j = tid & 15;
                bsum[tid] = bi[g * HDIM + jb + j] + bh[g * HDIM + jb + j];
            }
            __syncthreads();
        }

        float acc[2][8][4];
        #pragma unroll
        for (int fi = 0; fi < 2; ++fi)
            #pragma unroll
            for (int nt = 0; nt < 8; ++nt)
                #pragma unroll
                for (int q = 0; q < 4; ++q) acc[fi][nt][q] = 0.0f;

        // prefetch A fragments of chunk c (f32, exact MMA-fragment elements)
        auto pf = [&](int c, float2* buf) {
            const float* base; size_t rs;
            if (c < 2) { base = x + (size_t)b0 * TLEN * IDIM + (size_t)t * IDIM + c * 64; rs = (size_t)TLEN * IDIM; }
            else       { base = hin + (size_t)b0 * HDIM + (c - 2) * 64; rs = HDIM; }
            #pragma unroll
            for (int ki = 0; ki < 2; ++ki) {
                const int ks = kp + 2 * ki;
                #pragma unroll
                for (int fi = 0; fi < 2; ++fi)
                    #pragma unroll
                    for (int q = 0; q < 4; ++q) {
                        int r  = 32 * p + fi * 16 + lq + (q & 1) * 8;
                        int kk = ks * 16 + lr + (q >> 1) * 8;
                        buf[ki * 8 + fi * 4 + q] = __ldcg((const float2*)(base + (size_t)r * rs + kk));
                    }
            }
        };

        auto compute = [&](int c, const float2* buf) {
            const uint32_t wb = sb + OFF_WH + (uint32_t)c * 8192u;
            #pragma unroll
            for (int ki = 0; ki < 2; ++ki) {
                const int ks = kp + 2 * ki;
                uint32_t bh[16], bl[16];
                #pragma unroll
                for (int pp = 0; pp < 4; ++pp) {
                    uint32_t brow = (uint32_t)(pp * 16 + ((lane & 16) ? 8 : 0) + (lane & 7));
                    uint32_t boff = SWZ(brow * 128u + (uint32_t)ks * 32u + ((lane & 8) ? 16u : 0u));
                    ldm4(bh + 4 * pp, wb + boff);
                    ldm4(bl + 4 * pp, wb + 81920u + boff);
                }
                uint32_t ah[2][4], al[2][4];
                #pragma unroll
                for (int fi = 0; fi < 2; ++fi)
                    #pragma unroll
                    for (int q = 0; q < 4; ++q) {
                        float2 v = buf[ki * 8 + fi * 4 + q];
                        __nv_bfloat162 h2 = __floats2bfloat162_rn(v.x, v.y);
                        float rx = v.x - __bfloat162float(h2.x);
                        float ry = v.y - __bfloat162float(h2.y);
                        __nv_bfloat162 l2 = __floats2bfloat162_rn(rx, ry);
                        ah[fi][q] = *(uint32_t*)&h2;
                        al[fi][q] = *(uint32_t*)&l2;
                    }
                // pass-major: 16 independent accumulators between reuses
                #pragma unroll
                for (int fi = 0; fi < 2; ++fi)
                    #pragma unroll
                    for (int nt = 0; nt < 8; ++nt)
                        mma16816(acc[fi][nt], ah[fi], bh + 2 * nt);
                #pragma unroll
                for (int fi = 0; fi < 2; ++fi)
                    #pragma unroll
                    for (int nt = 0; nt < 8; ++nt)
                        mma16816(acc[fi][nt], al[fi], bh + 2 * nt);
                #pragma unroll
                for (int fi = 0; fi < 2; ++fi)
                    #pragma unroll
                    for (int nt = 0; nt < 8; ++nt)
                        mma16816(acc[fi][nt], ah[fi], bl + 2 * nt);
            }
        };

        // x-chunks (h-independent) run before the barrier wait -> overlap
        pf(0, bufA); pf(1, bufB);
        compute(0, bufA);
        compute(1, bufB);
        gb_wait(tid, by, gbase + 1 + (unsigned)s);   // group h from step s-1 ready
        pf(2, bufA);
        #pragma unroll 1
        for (int c = 2; c < 10; ++c) {
            float2* cur = (c & 1) ? bufB : bufA;
            float2* nxt = (c & 1) ? bufA : bufB;
            if (c < 9) pf(c + 1, nxt);
            compute(c, cur);
        }

        // ---- bidirectional split-K exchange: warp kp keeps half fi=kp ----
        const uint32_t send = sb + OFF_XCH + (uint32_t)p * 9216u + (uint32_t)(1 - kp) * 4608u;
        const uint32_t recv = sb + OFF_XCH + (uint32_t)p * 9216u + (uint32_t)kp * 4608u;
        {
            const int fiS = 1 - kp;
            #pragma unroll
            for (int nt = 0; nt < 8; ++nt)
                #pragma unroll
                for (int qr = 0; qr < 2; ++qr) {
                    uint32_t a = send + (uint32_t)(lq + 8 * qr) * 288u
                                      + (uint32_t)(nt * 8 + lr) * 4u;
                    asm volatile("st.shared.v2.f32 [%0], {%1,%2};" :: "r"(a),
                        "f"(acc[fiS][nt][2 * qr]), "f"(acc[fiS][nt][2 * qr + 1]) : "memory");
                }
        }
        __syncthreads();
        {
            #pragma unroll
            for (int nt = 0; nt < 8; ++nt)
                #pragma unroll
                for (int qr = 0; qr < 2; ++qr) {
                    uint32_t a = recv + (uint32_t)(lq + 8 * qr) * 288u
                                      + (uint32_t)(nt * 8 + lr) * 4u;
                    float px, py;
                    asm volatile("ld.shared.v2.f32 {%0,%1}, [%2];" : "=f"(px), "=f"(py) : "r"(a));
                    acc[kp][nt][2 * qr]     += px;
                    acc[kp][nt][2 * qr + 1] += py;
                }
        }

        // ---- fused gate epilogue: BOTH warps; warp kp owns rows 32p+kp*16 ----
        {
            #pragma unroll
            for (int qr = 0; qr < 2; ++qr) {
                const int r = 32 * p + kp * 16 + lq + qr * 8;
                const int b = b0 + r;
                #pragma unroll
                for (int nh = 0; nh < 2; ++nh) {
                    float hv[2];
                    #pragma unroll
                    for (int e = 0; e < 2; ++e) {
                        const int q = 2 * qr + e;
                        const int j = nh * 8 + lr + e;
                        float vi = acc[kp][nh][q]     + bsum[j];
                        float vf = acc[kp][2 + nh][q] + bsum[16 + j];
                        float vg = acc[kp][4 + nh][q] + bsum[32 + j];
                        float vo = acc[kp][6 + nh][q] + bsum[48 + j];
                        float iv = sig_(vi), fv = sig_(vf), gv = tnh_(vg), ov = sig_(vo);
                        const int ci = qr * 4 + nh * 2 + e;
                        float cn = fv * cst[ci] + iv * gv;
                        cst[ci] = cn;
                        hv[e] = ov * tnh_(cn);
                    }
                    *(float2*)(hout + (size_t)b * HDIM + jb + nh * 8 + lr) =
                        make_float2(hv[0], hv[1]);
                }
            }
        }
        __syncthreads();
        gb_arrive(tid, by, gbase + 2 + (unsigned)s);
    }

    // ---- fc epilogue: final h is in g_h[0] (group-local) ----
    gb_wait(tid, by, gbase + 1 + 2 * TLEN);
    if (blockIdx.x == 0) {
        for (int r = wid; r < 128; r += 8) {
            const float* hr = g_h[0] + (size_t)(b0 + r) * HDIM;
            float ssum = 0.0f;
            #pragma unroll 4
            for (int k = lane; k < HDIM; k += 32) ssum += __ldcg(hr + k) * fcW[k];
            #pragma unroll
            for (int o = 16; o; o >>= 1) ssum += __shfl_xor_sync(0xffffffffu, ssum, o);
            if (lane == 0) out[b0 + r] = ssum + fcb[0];
        }
    }
}

extern "C" void kernel_launch(void* const* d_in, const int* in_sizes, int n_in,
                              void* d_out, int out_size)
{
    (void)in_sizes; (void)n_in; (void)out_size;
    cudaFuncSetAttribute(lstm_mma10, cudaFuncAttributeMaxDynamicSharedMemorySize, SMEM_BYTES);
    dim3 grid(32, 4);   // 32 h-slices x 4 batch groups = 128 CTAs (1/SM)
    lstm_mma10<<<grid, 256, SMEM_BYTES>>>(
        (const float*)d_in[0],
        (const float*)d_in[1], (const float*)d_in[2],
        (const float*)d_in[3], (const float*)d_in[4],
        (const float*)d_in[5], (const float*)d_in[6],
        (const float*)d_in[7], (const float*)d_in[8],
        (const float*)d_in[9], (const float*)d_in[10],
        (float*)d_out);
}

// round 16
// speedup vs baseline: 1.2311x; 1.2311x over previous
#include <cuda_runtime.h>
#include <cuda_bf16.h>
#include <cstdint>

#define BATCH 512
#define TLEN  512
#define IDIM  128
#define HDIM  512
#define NCTA  128

#define OFF_BSUM  0
#define OFF_XCH   1024                    // 4 pairs * 2 halves * 4608B
#define OFF_WH    38912
#define OFF_WL    (OFF_WH + 81920)
#define SMEM_BYTES (OFF_WL + 81920)       // 202752

__device__ float    g_h[2][BATCH * HDIM];
__device__ unsigned g_count, g_gen;

__device__ __forceinline__ uint32_t smem_u32(const void* p) {
    uint32_t a;
    asm("{ .reg .u64 t; cvta.to.shared.u64 t, %1; cvt.u32.u64 %0, t; }" : "=r"(a) : "l"(p));
    return a;
}
#define SWZ(o) ((o) ^ (((o) >> 3) & 0x70))

__device__ __forceinline__ void ldm4(uint32_t* r, uint32_t addr) {
    asm volatile("ldmatrix.sync.aligned.m8n8.x4.shared.b16 {%0,%1,%2,%3}, [%4];"
        : "=r"(r[0]), "=r"(r[1]), "=r"(r[2]), "=r"(r[3]) : "r"(addr));
}
__device__ __forceinline__ void mma16816(float* d, const uint32_t* a, const uint32_t* b) {
    asm volatile("mma.sync.aligned.m16n8k16.row.col.f32.bf16.bf16.f32 "
        "{%0,%1,%2,%3},{%4,%5,%6,%7},{%8,%9},{%0,%1,%2,%3};"
        : "+f"(d[0]), "+f"(d[1]), "+f"(d[2]), "+f"(d[3])
        : "r"(a[0]), "r"(a[1]), "r"(a[2]), "r"(a[3]), "r"(b[0]), "r"(b[1]));
}

// ---- light grid barrier: acq_rel arrival + release/acquire generation ----
__device__ __forceinline__ void gb_arrive(int tid, unsigned target) {
    if (tid == 0) {
        unsigned old;
        asm volatile("atom.acq_rel.gpu.global.add.u32 %0, [%1], 1;"
                     : "=r"(old) : "l"(&g_count) : "memory");
        if (old == NCTA - 1) {
            asm volatile("st.relaxed.gpu.global.u32 [%0], %1;" :: "l"(&g_count), "r"(0u) : "memory");
            asm volatile("st.release.gpu.global.u32 [%0], %1;" :: "l"(&g_gen), "r"(target) : "memory");
        }
    }
}
__device__ __forceinline__ void gb_wait(int tid, unsigned target) {
    if (tid == 0) {
        unsigned g;
        do {
            asm volatile("ld.acquire.gpu.global.u32 %0, [%1];" : "=r"(g) : "l"(&g_gen) : "memory");
        } while ((int)(g - target) < 0);
    }
    __syncthreads();
}

// hi/lo bf16 split of a float4, stored as two 8-byte shared words (weights).
__device__ __forceinline__ void cvt_sts(float4 v, uint32_t ah, uint32_t al) {
    __nv_bfloat162 h0 = __floats2bfloat162_rn(v.x, v.y);
    __nv_bfloat162 h1 = __floats2bfloat162_rn(v.z, v.w);
    float lx = v.x - __bfloat162float(h0.x), ly = v.y - __bfloat162float(h0.y);
    float lz = v.z - __bfloat162float(h1.x), lw = v.w - __bfloat162float(h1.y);
    __nv_bfloat162 l0 = __floats2bfloat162_rn(lx, ly);
    __nv_bfloat162 l1 = __floats2bfloat162_rn(lz, lw);
    uint64_t hv = ((uint64_t)*(uint32_t*)&h1 << 32) | *(uint32_t*)&h0;
    uint64_t lv = ((uint64_t)*(uint32_t*)&l1 << 32) | *(uint32_t*)&l0;
    asm volatile("st.shared.b64 [%0], %1;" :: "r"(ah), "l"(hv) : "memory");
    asm volatile("st.shared.b64 [%0], %1;" :: "r"(al), "l"(lv) : "memory");
}

__device__ __forceinline__ float sig_(float x) { return 1.0f / (1.0f + __expf(-x)); }
__device__ __forceinline__ float tnh_(float x) { return 2.0f / (1.0f + __expf(-2.0f * x)) - 1.0f; }

__global__ void __launch_bounds__(256, 1) lstm_mma11(
    const float* __restrict__ x,
    const float* __restrict__ eWih, const float* __restrict__ eWhh,
    const float* __restrict__ ebih, const float* __restrict__ ebhh,
    const float* __restrict__ dWih, const float* __restrict__ dWhh,
    const float* __restrict__ dbih, const float* __restrict__ dbhh,
    const float* __restrict__ fcW,  const float* __restrict__ fcb,
    float* __restrict__ out)
{
    extern __shared__ __align__(1024) char smem[];
    const uint32_t sb = smem_u32(smem);
    const int tid = threadIdx.x, wid = tid >> 5, lane = tid & 31;
    const int p  = wid >> 1;            // pair/tile 0..3 -> rows 32p..32p+31
    const int kp = wid & 1;             // k-parity within pair
    const int jb = blockIdx.x * 16;     // h-col base
    const int b0 = blockIdx.y * 128;    // batch base
    const int lq = lane >> 2;           // 0..7
    const int lr = (lane & 3) << 1;     // 0,2,4,6

    float* bsum = (float*)(smem + OFF_BSUM);
    char*  xch  = smem + OFF_XCH + p * 9216;   // 32 rows x 72 f32 (288B stride)

    unsigned gbase = 0;
    if (tid == 0) gbase = *(volatile unsigned*)&g_gen;

    // zero this CTA's slice of h0
    for (int i = tid; i < 2048; i += 256) {
        int r = i >> 5, c = i & 31;
        g_h[0][(size_t)(b0 + r) * HDIM + jb + c] = 0.0f;
    }
    float cst[16];
    #pragma unroll
    for (int j = 0; j < 16; ++j) cst[j] = 0.0f;

    gb_arrive(tid, gbase + 1);
    gb_wait(tid, gbase + 1);

    // converted A operands: [ki*16 + fi*8 + q] = hi, [.. + 4 + q] = lo
    uint32_t bufA[32], bufB[32];

    #pragma unroll 1
    for (int s = 0; s < 2 * TLEN; ++s) {
        const int dec = (s >= TLEN) ? 1 : 0;
        const int t = dec ? s - TLEN : s;
        const float* hin  = g_h[s & 1];
        float*       hout = g_h[(s + 1) & 1];

        // ---- per-phase weight + bias preload (hi/lo bf16 in SMEM) ----
        if (s == 0 || s == TLEN) {
            const float* Wih = dec ? dWih : eWih;
            const float* Whh = dec ? dWhh : eWhh;
            const float* bi  = dec ? dbih : ebih;
            const float* bh  = dec ? dbhh : ebhh;
            __syncthreads();
            #pragma unroll 1
            for (int i = tid; i < 10240; i += 256) {   // 64 rows x 160 float4
                int rl = i / 160, k4 = i % 160;
                int c = k4 >> 4, kin = k4 & 15;
                int grow = (rl >> 4) * HDIM + jb + (rl & 15);
                const float* sp = (c < 2) ? (Wih + (size_t)grow * IDIM + c * 64 + kin * 4)
                                          : (Whh + (size_t)grow * HDIM + (c - 2) * 64 + kin * 4);
                float4 v = *(const float4*)sp;
                uint32_t off = (uint32_t)c * 8192u + SWZ((uint32_t)rl * 128u + (uint32_t)kin * 8u);
                cvt_sts(v, sb + OFF_WH + off, sb + OFF_WL + off);
            }
            if (tid < 64) {
                int g = tid >> 4, j = tid & 15;
                bsum[tid] = bi[g * HDIM + jb + j] + bh[g * HDIM + jb + j];
            }
            __syncthreads();
        }

        float acc[2][8][4];
        #pragma unroll
        for (int fi = 0; fi < 2; ++fi)
            #pragma unroll
            for (int nt = 0; nt < 8; ++nt)
                #pragma unroll
                for (int q = 0; q < 4; ++q) acc[fi][nt][q] = 0.0f;

        // prefetch + CONVERT A fragments of chunk c (hi/lo bf16 in regs)
        auto pf_cvt = [&](int c, uint32_t* buf) {
            const float* base; size_t rs;
            if (c < 2) { base = x + (size_t)b0 * TLEN * IDIM + (size_t)t * IDIM + c * 64; rs = (size_t)TLEN * IDIM; }
            else       { base = hin + (size_t)b0 * HDIM + (c - 2) * 64; rs = HDIM; }
            #pragma unroll
            for (int ki = 0; ki < 2; ++ki) {
                const int ks = kp + 2 * ki;
                #pragma unroll
                for (int fi = 0; fi < 2; ++fi)
                    #pragma unroll
                    for (int q = 0; q < 4; ++q) {
                        int r  = 32 * p + fi * 16 + lq + (q & 1) * 8;
                        int kk = ks * 16 + lr + (q >> 1) * 8;
                        float2 v = __ldcg((const float2*)(base + (size_t)r * rs + kk));
                        __nv_bfloat162 h2 = __floats2bfloat162_rn(v.x, v.y);
                        float rx = v.x - __bfloat162float(h2.x);
                        float ry = v.y - __bfloat162float(h2.y);
                        __nv_bfloat162 l2 = __floats2bfloat162_rn(rx, ry);
                        buf[ki * 16 + fi * 8 + q]     = *(uint32_t*)&h2;
                        buf[ki * 16 + fi * 8 + 4 + q] = *(uint32_t*)&l2;
                    }
            }
        };

        // pure ldsm + MMA (A already converted) — tensor pipe stays fed;
        // next chunk's LDG+cvt instructions interleave into this stream.
        auto compute = [&](int c, const uint32_t* A) {
            const uint32_t wb = sb + OFF_WH + (uint32_t)c * 8192u;
            #pragma unroll
            for (int ki = 0; ki < 2; ++ki) {
                const int ks = kp + 2 * ki;
                uint32_t bh[16], bl[16];
                #pragma unroll
                for (int pp = 0; pp < 4; ++pp) {
                    uint32_t brow = (uint32_t)(pp * 16 + ((lane & 16) ? 8 : 0) + (lane & 7));
                    uint32_t boff = SWZ(brow * 128u + (uint32_t)ks * 32u + ((lane & 8) ? 16u : 0u));
                    ldm4(bh + 4 * pp, wb + boff);
                    ldm4(bl + 4 * pp, wb + 81920u + boff);
                }
                // pass-major: 16 independent accumulators between reuses
                #pragma unroll
                for (int fi = 0; fi < 2; ++fi)
                    #pragma unroll
                    for (int nt = 0; nt < 8; ++nt)
                        mma16816(acc[fi][nt], A + ki * 16 + fi * 8, bh + 2 * nt);
                #pragma unroll
                for (int fi = 0; fi < 2; ++fi)
                    #pragma unroll
                    for (int nt = 0; nt < 8; ++nt)
                        mma16816(acc[fi][nt], A + ki * 16 + fi * 8 + 4, bh + 2 * nt);
                #pragma unroll
                for (int fi = 0; fi < 2; ++fi)
                    #pragma unroll
                    for (int nt = 0; nt < 8; ++nt)
                        mma16816(acc[fi][nt], A + ki * 16 + fi * 8, bl + 2 * nt);
            }
        };

        // x-chunks (h-independent) run before the barrier wait -> overlap
        pf_cvt(0, bufA); pf_cvt(1, bufB);
        compute(0, bufA);
        compute(1, bufB);
        gb_wait(tid, gbase + 1 + (unsigned)s);   // h from step s-1 ready
        pf_cvt(2, bufA);
        #pragma unroll 1
        for (int c = 2; c < 10; ++c) {
            uint32_t* cur = (c & 1) ? bufB : bufA;
            uint32_t* nxt = (c & 1) ? bufA : bufB;
            if (c < 9) pf_cvt(c + 1, nxt);
            compute(c, cur);
        }

        // ---- split-K exchange + fused gate epilogue ----
        if (kp) {
            #pragma unroll
            for (int fi = 0; fi < 2; ++fi)
                #pragma unroll
                for (int nt = 0; nt < 8; ++nt)
                    #pragma unroll
                    for (int qr = 0; qr < 2; ++qr) {
                        uint32_t rowl = (uint32_t)(fi * 16 + lq + qr * 8);
                        uint32_t col  = (uint32_t)(nt * 8 + lr);
                        *(float2*)(xch + rowl * 288 + col * 4) =
                            make_float2(acc[fi][nt][2 * qr], acc[fi][nt][2 * qr + 1]);
                    }
        }
        __syncthreads();
        if (!kp) {
            #pragma unroll
            for (int fi = 0; fi < 2; ++fi)
                #pragma unroll
                for (int nt = 0; nt < 8; ++nt)
                    #pragma unroll
                    for (int qr = 0; qr < 2; ++qr) {
                        uint32_t rowl = (uint32_t)(fi * 16 + lq + qr * 8);
                        uint32_t col  = (uint32_t)(nt * 8 + lr);
                        float2 pv = *(const float2*)(xch + rowl * 288 + col * 4);
                        acc[fi][nt][2 * qr]     += pv.x;
                        acc[fi][nt][2 * qr + 1] += pv.y;
                    }
            #pragma unroll
            for (int fi = 0; fi < 2; ++fi)
                #pragma unroll
                for (int qr = 0; qr < 2; ++qr) {
                    const int r = 32 * p + fi * 16 + lq + qr * 8;
                    const int b = b0 + r;
                    #pragma unroll
                    for (int nh = 0; nh < 2; ++nh) {
                        float hv[2];
                        #pragma unroll
                        for (int e = 0; e < 2; ++e) {
                            const int q = 2 * qr + e;
                            const int j = nh * 8 + lr + e;
                            float vi = acc[fi][nh][q]     + bsum[j];
                            float vf = acc[fi][2 + nh][q] + bsum[16 + j];
                            float vg = acc[fi][4 + nh][q] + bsum[32 + j];
                            float vo = acc[fi][6 + nh][q] + bsum[48 + j];
                            float iv = sig_(vi), fv = sig_(vf), gv = tnh_(vg), ov = sig_(vo);
                            const int ci = fi * 8 + qr * 4 + nh * 2 + e;
                            float cn = fv * cst[ci] + iv * gv;
                            cst[ci] = cn;
                            hv[e] = ov * tnh_(cn);
                        }
                        *(float2*)(hout + (size_t)b * HDIM + jb + nh * 8 + lr) =
                            make_float2(hv[0], hv[1]);
                    }
                }
        }
        __syncthreads();
        gb_arrive(tid, gbase + 2 + (unsigned)s);
    }

    // ---- fc epilogue: final h is in g_h[0] ----
    gb_wait(tid, gbase + 1 + 2 * TLEN);
    if (blockIdx.x == 0) {
        for (int r = wid; r < 128; r += 8) {
            const float* hr = g_h[0] + (size_t)(b0 + r) * HDIM;
            float ssum = 0.0f;
            #pragma unroll 4
            for (int k = lane; k < HDIM; k += 32) ssum += __ldcg(hr + k) * fcW[k];
            #pragma unroll
            for (int o = 16; o; o >>= 1) ssum += __shfl_xor_sync(0xffffffffu, ssum, o);
            if (lane == 0) out[b0 + r] = ssum + fcb[0];
        }
    }
}

extern "C" void kernel_launch(void* const* d_in, const int* in_sizes, int n_in,
                              void* d_out, int out_size)
{
    (void)in_sizes; (void)n_in; (void)out_size;
    cudaFuncSetAttribute(lstm_mma11, cudaFuncAttributeMaxDynamicSharedMemorySize, SMEM_BYTES);
    dim3 grid(32, 4);   // 32 h-slices x 4 batch groups = 128 CTAs (1/SM)
    lstm_mma11<<<grid, 256, SMEM_BYTES>>>(
        (const float*)d_in[0],
        (const float*)d_in[1], (const float*)d_in[2],
        (const float*)d_in[3], (const float*)d_in[4],
        (const float*)d_in[5], (const float*)d_in[6],
        (const float*)d_in[7], (const float*)d_in[8],
        (const float*)d_in[9], (const float*)d_in[10],
        (float*)d_out);
}

// round 17
// speedup vs baseline: 1.2419x; 1.0088x over previous
#include <cuda_runtime.h>
#include <cuda_bf16.h>
#include <cstdint>

#define BATCH 512
#define TLEN  512
#define IDIM  128
#define HDIM  512
#define NCTA  128

#define OFF_BSUM  0
#define OFF_XCH   1024                    // 4 pairs * 2 halves * 4608B
#define OFF_WH    38912
#define OFF_WL    (OFF_WH + 81920)
#define SMEM_BYTES (OFF_WL + 81920)       // 202752

__device__ float    g_h[2][BATCH * HDIM];
__device__ unsigned g_count, g_gen;

__device__ __forceinline__ uint32_t smem_u32(const void* p) {
    uint32_t a;
    asm("{ .reg .u64 t; cvta.to.shared.u64 t, %1; cvt.u32.u64 %0, t; }" : "=r"(a) : "l"(p));
    return a;
}
#define SWZ(o) ((o) ^ (((o) >> 3) & 0x70))

__device__ __forceinline__ void ldm4(uint32_t* r, uint32_t addr) {
    asm volatile("ldmatrix.sync.aligned.m8n8.x4.shared.b16 {%0,%1,%2,%3}, [%4];"
        : "=r"(r[0]), "=r"(r[1]), "=r"(r[2]), "=r"(r[3]) : "r"(addr));
}
__device__ __forceinline__ void mma16816(float* d, const uint32_t* a, const uint32_t* b) {
    asm volatile("mma.sync.aligned.m16n8k16.row.col.f32.bf16.bf16.f32 "
        "{%0,%1,%2,%3},{%4,%5,%6,%7},{%8,%9},{%0,%1,%2,%3};"
        : "+f"(d[0]), "+f"(d[1]), "+f"(d[2]), "+f"(d[3])
        : "r"(a[0]), "r"(a[1]), "r"(a[2]), "r"(a[3]), "r"(b[0]), "r"(b[1]));
}

// ---- light grid barrier: acq_rel arrival + release/acquire generation ----
__device__ __forceinline__ void gb_arrive(int tid, unsigned target) {
    if (tid == 0) {
        unsigned old;
        asm volatile("atom.acq_rel.gpu.global.add.u32 %0, [%1], 1;"
                     : "=r"(old) : "l"(&g_count) : "memory");
        if (old == NCTA - 1) {
            asm volatile("st.relaxed.gpu.global.u32 [%0], %1;" :: "l"(&g_count), "r"(0u) : "memory");
            asm volatile("st.release.gpu.global.u32 [%0], %1;" :: "l"(&g_gen), "r"(target) : "memory");
        }
    }
}
__device__ __forceinline__ void gb_wait(int tid, unsigned target) {
    if (tid == 0) {
        unsigned g;
        do {
            asm volatile("ld.acquire.gpu.global.u32 %0, [%1];" : "=r"(g) : "l"(&g_gen) : "memory");
        } while ((int)(g - target) < 0);
    }
    __syncthreads();
}

// hi/lo bf16 split of a float4, stored as two 8-byte shared words (weights).
__device__ __forceinline__ void cvt_sts(float4 v, uint32_t ah, uint32_t al) {
    __nv_bfloat162 h0 = __floats2bfloat162_rn(v.x, v.y);
    __nv_bfloat162 h1 = __floats2bfloat162_rn(v.z, v.w);
    float lx = v.x - __bfloat162float(h0.x), ly = v.y - __bfloat162float(h0.y);
    float lz = v.z - __bfloat162float(h1.x), lw = v.w - __bfloat162float(h1.y);
    __nv_bfloat162 l0 = __floats2bfloat162_rn(lx, ly);
    __nv_bfloat162 l1 = __floats2bfloat162_rn(lz, lw);
    uint64_t hv = ((uint64_t)*(uint32_t*)&h1 << 32) | *(uint32_t*)&h0;
    uint64_t lv = ((uint64_t)*(uint32_t*)&l1 << 32) | *(uint32_t*)&l0;
    asm volatile("st.shared.b64 [%0], %1;" :: "r"(ah), "l"(hv) : "memory");
    asm volatile("st.shared.b64 [%0], %1;" :: "r"(al), "l"(lv) : "memory");
}

__device__ __forceinline__ float sig_(float x) { return 1.0f / (1.0f + __expf(-x)); }
__device__ __forceinline__ float tnh_(float x) { return 2.0f / (1.0f + __expf(-2.0f * x)) - 1.0f; }

__global__ void __launch_bounds__(256, 1) lstm_mma12(
    const float* __restrict__ x,
    const float* __restrict__ eWih, const float* __restrict__ eWhh,
    const float* __restrict__ ebih, const float* __restrict__ ebhh,
    const float* __restrict__ dWih, const float* __restrict__ dWhh,
    const float* __restrict__ dbih, const float* __restrict__ dbhh,
    const float* __restrict__ fcW,  const float* __restrict__ fcb,
    float* __restrict__ out)
{
    extern __shared__ __align__(1024) char smem[];
    const uint32_t sb = smem_u32(smem);
    const int tid = threadIdx.x, wid = tid >> 5, lane = tid & 31;
    const int p  = wid >> 1;            // pair/tile 0..3 -> rows 32p..32p+31
    const int kp = wid & 1;             // k-parity within pair
    const int jb = blockIdx.x * 16;     // h-col base
    const int b0 = blockIdx.y * 128;    // batch base
    const int lq = lane >> 2;           // 0..7
    const int lr = (lane & 3) << 1;     // 0,2,4,6

    float* bsum = (float*)(smem + OFF_BSUM);
    char*  xch  = smem + OFF_XCH + p * 9216;   // 32 rows x 72 f32 (288B stride)

    unsigned gbase = 0;
    if (tid == 0) gbase = *(volatile unsigned*)&g_gen;

    // zero this CTA's slice of h0
    for (int i = tid; i < 2048; i += 256) {
        int r = i >> 5, c = i & 31;
        g_h[0][(size_t)(b0 + r) * HDIM + jb + c] = 0.0f;
    }
    float cst[16];
    #pragma unroll
    for (int j = 0; j < 16; ++j) cst[j] = 0.0f;

    gb_arrive(tid, gbase + 1);
    gb_wait(tid, gbase + 1);

    float2 fA[16], fB[16];   // raw f32 loads (double buffer)
    uint32_t U[32];          // converted operands for the current chunk

    #pragma unroll 1
    for (int s = 0; s < 2 * TLEN; ++s) {
        const int dec = (s >= TLEN) ? 1 : 0;
        const int t = dec ? s - TLEN : s;
        const float* hin  = g_h[s & 1];
        float*       hout = g_h[(s + 1) & 1];

        // ---- per-phase weight + bias preload (hi/lo bf16 in SMEM) ----
        if (s == 0 || s == TLEN) {
            const float* Wih = dec ? dWih : eWih;
            const float* Whh = dec ? dWhh : eWhh;
            const float* bi  = dec ? dbih : ebih;
            const float* bh  = dec ? dbhh : ebhh;
            __syncthreads();
            #pragma unroll 1
            for (int i = tid; i < 10240; i += 256) {   // 64 rows x 160 float4
                int rl = i / 160, k4 = i % 160;
                int c = k4 >> 4, kin = k4 & 15;
                int grow = (rl >> 4) * HDIM + jb + (rl & 15);
                const float* sp = (c < 2) ? (Wih + (size_t)grow * IDIM + c * 64 + kin * 4)
                                          : (Whh + (size_t)grow * HDIM + (c - 2) * 64 + kin * 4);
                float4 v = *(const float4*)sp;
                uint32_t off = (uint32_t)c * 8192u + SWZ((uint32_t)rl * 128u + (uint32_t)kin * 8u);
                cvt_sts(v, sb + OFF_WH + off, sb + OFF_WL + off);
            }
            if (tid < 64) {
                int g = tid >> 4, j = tid & 15;
                bsum[tid] = bi[g * HDIM + jb + j] + bh[g * HDIM + jb + j];
            }
            __syncthreads();
        }

        float acc[2][8][4];
        #pragma unroll
        for (int fi = 0; fi < 2; ++fi)
            #pragma unroll
            for (int nt = 0; nt < 8; ++nt)
                #pragma unroll
                for (int q = 0; q < 4; ++q) acc[fi][nt][q] = 0.0f;

        // pure prefetch: LDG f32 fragments into float2 regs (no dependence)
        auto pf_load = [&](int c, float2* buf) {
            const float* base; size_t rs;
            if (c < 2) { base = x + (size_t)b0 * TLEN * IDIM + (size_t)t * IDIM + c * 64; rs = (size_t)TLEN * IDIM; }
            else       { base = hin + (size_t)b0 * HDIM + (c - 2) * 64; rs = HDIM; }
            #pragma unroll
            for (int ki = 0; ki < 2; ++ki) {
                const int ks = kp + 2 * ki;
                #pragma unroll
                for (int fi = 0; fi < 2; ++fi)
                    #pragma unroll
                    for (int q = 0; q < 4; ++q) {
                        int r  = 32 * p + fi * 16 + lq + (q & 1) * 8;
                        int kk = ks * 16 + lr + (q >> 1) * 8;
                        buf[ki * 8 + fi * 4 + q] = __ldcg((const float2*)(base + (size_t)r * rs + kk));
                    }
            }
        };

        // convert a chunk loaded >=1 chunk ago: float2 -> bf16 hi/lo regs
        auto cvt_stage = [&](const float2* buf) {
            #pragma unroll
            for (int ki = 0; ki < 2; ++ki)
                #pragma unroll
                for (int fi = 0; fi < 2; ++fi)
                    #pragma unroll
                    for (int q = 0; q < 4; ++q) {
                        float2 v = buf[ki * 8 + fi * 4 + q];
                        __nv_bfloat162 h2 = __floats2bfloat162_rn(v.x, v.y);
                        float rx = v.x - __bfloat162float(h2.x);
                        float ry = v.y - __bfloat162float(h2.y);
                        __nv_bfloat162 l2 = __floats2bfloat162_rn(rx, ry);
                        U[ki * 16 + fi * 8 + q]     = *(uint32_t*)&h2;
                        U[ki * 16 + fi * 8 + 4 + q] = *(uint32_t*)&l2;
                    }
        };

        // pure ldsm + MMA (operands in U)
        auto compute = [&](int c) {
            const uint32_t wb = sb + OFF_WH + (uint32_t)c * 8192u;
            #pragma unroll
            for (int ki = 0; ki < 2; ++ki) {
                const int ks = kp + 2 * ki;
                uint32_t bh[16], bl[16];
                #pragma unroll
                for (int pp = 0; pp < 4; ++pp) {
                    uint32_t brow = (uint32_t)(pp * 16 + ((lane & 16) ? 8 : 0) + (lane & 7));
                    uint32_t boff = SWZ(brow * 128u + (uint32_t)ks * 32u + ((lane & 8) ? 16u : 0u));
                    ldm4(bh + 4 * pp, wb + boff);
                    ldm4(bl + 4 * pp, wb + 81920u + boff);
                }
                // pass-major: 16 independent accumulators between reuses
                #pragma unroll
                for (int fi = 0; fi < 2; ++fi)
                    #pragma unroll
                    for (int nt = 0; nt < 8; ++nt)
                        mma16816(acc[fi][nt], U + ki * 16 + fi * 8, bh + 2 * nt);
                #pragma unroll
                for (int fi = 0; fi < 2; ++fi)
                    #pragma unroll
                    for (int nt = 0; nt < 8; ++nt)
                        mma16816(acc[fi][nt], U + ki * 16 + fi * 8 + 4, bh + 2 * nt);
                #pragma unroll
                for (int fi = 0; fi < 2; ++fi)
                    #pragma unroll
                    for (int nt = 0; nt < 8; ++nt)
                        mma16816(acc[fi][nt], U + ki * 16 + fi * 8, bl + 2 * nt);
            }
        };

        // pre-wait: load both x-chunks; compute chunk 0 only (chunk 1 held
        // in reserve to cover the post-wait h-load latency).
        pf_load(0, fA);
        pf_load(1, fB);
        cvt_stage(fA);
        compute(0);
        gb_wait(tid, gbase + 1 + (unsigned)s);   // h from step s-1 ready
        pf_load(2, fA);      // fA free (chunk 0 already converted)
        cvt_stage(fB);
        compute(1);          // covers pf_load(2) latency
        #pragma unroll 1
        for (int c = 2; c < 10; ++c) {
            float2* cur = (c & 1) ? fB : fA;
            float2* nxt = (c & 1) ? fA : fB;
            if (c < 9) pf_load(c + 1, nxt);
            cvt_stage(cur);   // loads for c issued one full chunk ago
            compute(c);
        }

        // ---- split-K exchange + fused gate epilogue ----
        if (kp) {
            #pragma unroll
            for (int fi = 0; fi < 2; ++fi)
                #pragma unroll
                for (int nt = 0; nt < 8; ++nt)
                    #pragma unroll
                    for (int qr = 0; qr < 2; ++qr) {
                        uint32_t rowl = (uint32_t)(fi * 16 + lq + qr * 8);
                        uint32_t col  = (uint32_t)(nt * 8 + lr);
                        *(float2*)(xch + rowl * 288 + col * 4) =
                            make_float2(acc[fi][nt][2 * qr], acc[fi][nt][2 * qr + 1]);
                    }
        }
        __syncthreads();
        if (!kp) {
            #pragma unroll
            for (int fi = 0; fi < 2; ++fi)
                #pragma unroll
                for (int nt = 0; nt < 8; ++nt)
                    #pragma unroll
                    for (int qr = 0; qr < 2; ++qr) {
                        uint32_t rowl = (uint32_t)(fi * 16 + lq + qr * 8);
                        uint32_t col  = (uint32_t)(nt * 8 + lr);
                        float2 pv = *(const float2*)(xch + rowl * 288 + col * 4);
                        acc[fi][nt][2 * qr]     += pv.x;
                        acc[fi][nt][2 * qr + 1] += pv.y;
                    }
            #pragma unroll
            for (int fi = 0; fi < 2; ++fi)
                #pragma unroll
                for (int qr = 0; qr < 2; ++qr) {
                    const int r = 32 * p + fi * 16 + lq + qr * 8;
                    const int b = b0 + r;
                    #pragma unroll
                    for (int nh = 0; nh < 2; ++nh) {
                        float hv[2];
                        #pragma unroll
                        for (int e = 0; e < 2; ++e) {
                            const int q = 2 * qr + e;
                            const int j = nh * 8 + lr + e;
                            float vi = acc[fi][nh][q]     + bsum[j];
                            float vf = acc[fi][2 + nh][q] + bsum[16 + j];
                            float vg = acc[fi][4 + nh][q] + bsum[32 + j];
                            float vo = acc[fi][6 + nh][q] + bsum[48 + j];
                            float iv = sig_(vi), fv = sig_(vf), gv = tnh_(vg), ov = sig_(vo);
                            const int ci = fi * 8 + qr * 4 + nh * 2 + e;
                            float cn = fv * cst[ci] + iv * gv;
                            cst[ci] = cn;
                            hv[e] = ov * tnh_(cn);
                        }
                        *(float2*)(hout + (size_t)b * HDIM + jb + nh * 8 + lr) =
                            make_float2(hv[0], hv[1]);
                    }
                }
        }
        __syncthreads();
        gb_arrive(tid, gbase + 2 + (unsigned)s);
    }

    // ---- fc epilogue: final h is in g_h[0] ----
    gb_wait(tid, gbase + 1 + 2 * TLEN);
    if (blockIdx.x == 0) {
        for (int r = wid; r < 128; r += 8) {
            const float* hr = g_h[0] + (size_t)(b0 + r) * HDIM;
            float ssum = 0.0f;
            #pragma unroll 4
            for (int k = lane; k < HDIM; k += 32) ssum += __ldcg(hr + k) * fcW[k];
            #pragma unroll
            for (int o = 16; o; o >>= 1) ssum += __shfl_xor_sync(0xffffffffu, ssum, o);
            if (lane == 0) out[b0 + r] = ssum + fcb[0];
        }
    }
}

extern "C" void kernel_launch(void* const* d_in, const int* in_sizes, int n_in,
                              void* d_out, int out_size)
{
    (void)in_sizes; (void)n_in; (void)out_size;
    cudaFuncSetAttribute(lstm_mma12, cudaFuncAttributeMaxDynamicSharedMemorySize, SMEM_BYTES);
    dim3 grid(32, 4);   // 32 h-slices x 4 batch groups = 128 CTAs (1/SM)
    lstm_mma12<<<grid, 256, SMEM_BYTES>>>(
        (const float*)d_in[0],
        (const float*)d_in[1], (const float*)d_in[2],
        (const float*)d_in[3], (const float*)d_in[4],
        (const float*)d_in[5], (const float*)d_in[6],
        (const float*)d_in[7], (const float*)d_in[8],
        (const float*)d_in[9], (const float*)d_in[10],
        (float*)d_out);
}